// round 16
// baseline (speedup 1.0000x reference)
#include <cuda_runtime.h>
#include <math.h>

// HybridBasisFunction: out = wavelet(xc) + sigmoid(alpha) * spline(xc), xc = clamp(x,0,1)
//
// Piecewise-affine reformulation: with j = floor(16*xc) (j in [0,16]),
//   - wavelet level-l sign = +1 iff bit (4-l) of j is 0   (exact: *16 is exact in fp32)
//   - spline segment k = j>>2 is constant within a bucket, lerp is affine in xc
// => out = A[j] + B[j]*xc with a 17-entry LUT in shared memory (conflict-free).
//
// FINAL (converged; reproduced three times: 76.0/76.4/76.8us kernel,
// 6.27-6.33 TB/s, DRAM 79.2-79.8%): 16384 blocks x 256 thr x 4 float4
// (16KB contiguous tile per CTA), batch-4 front-loaded LDG.128,
// evict-first (.cs) both streams.
//
// Tile-size curve (kernel us / DRAM%): 64KB 79.1/77.5; 32KB 77.8/78.2;
// 16KB 76.0-76.8/79.2-79.8 (min); 8KB 77.6/78.3. All other axes neutral or
// worse: cache/store policy combos, MLP 4 vs 8, occupancy 65-88%, L2
// cross-replay pinning, persistent-strided (83.2), 226KB chunks (87.5),
// 6-wave uneven chunks (79.5). Kernel is at the mixed 1:1 R/W HBM ceiling
// with irreducible traffic (256MB read + 256MB write).

#define NTHR 256
#define VPT  4    // float4 per thread (1 group of 4); 16KB contiguous tile per CTA

__device__ __forceinline__ float hb_eval(float v, const float* __restrict__ sA,
                                         const float* __restrict__ sB) {
    float xc = fminf(fmaxf(v, 0.0f), 1.0f);
    int j = (int)(xc * 16.0f);           // exact; j in [0,16]
    return fmaf(sB[j], xc, sA[j]);
}

__device__ __forceinline__ void hb_lut_init(const float* __restrict__ wc,
                                            const float* __restrict__ sc,
                                            const float* __restrict__ al,
                                            float* __restrict__ sA,
                                            float* __restrict__ sB) {
    if (threadIdx.x < 17) {
        int j = threadIdx.x;
        float sig = 1.0f / (1.0f + expf(-al[0]));
        float A, B;
        if (j < 16) {
            float wv = wc[0];
            wv += ((j >> 3) & 1) ? -wc[1] : wc[1];
            wv += ((j >> 2) & 1) ? -wc[2] : wc[2];
            wv += ((j >> 1) & 1) ? -wc[3] : wc[3];
            wv += ( j       & 1) ? -wc[4] : wc[4];
            int k = j >> 2;
            float c0 = sc[k], c1 = sc[k + 1];
            float d  = sig * (c1 - c0);
            A = wv + sig * c0 - (float)k * d;
            B = 4.0f * d;
        } else {
            A = wc[0] + sig * sc[4];   // xc == 1.0 exactly
            B = 0.0f;
        }
        sA[j] = A;
        sB[j] = B;
    }
    __syncthreads();
}

// Main kernel: each block owns a contiguous tile of NTHR*VPT float4s, exact fit.
__global__ void __launch_bounds__(NTHR)
hybrid_basis_main(const float4* __restrict__ x4, float4* __restrict__ o4,
                  const float* __restrict__ wc, const float* __restrict__ sc,
                  const float* __restrict__ al)
{
    __shared__ float sA[17];
    __shared__ float sB[17];
    hb_lut_init(wc, sc, al, sA, sB);

    int base = blockIdx.x * (NTHR * VPT) + threadIdx.x;

    int i0 = base;
    int i1 = base + NTHR;
    int i2 = base + 2 * NTHR;
    int i3 = base + 3 * NTHR;

    float4 v0 = __ldcs(x4 + i0);
    float4 v1 = __ldcs(x4 + i1);
    float4 v2 = __ldcs(x4 + i2);
    float4 v3 = __ldcs(x4 + i3);

    v0.x = hb_eval(v0.x, sA, sB); v0.y = hb_eval(v0.y, sA, sB);
    v0.z = hb_eval(v0.z, sA, sB); v0.w = hb_eval(v0.w, sA, sB);
    v1.x = hb_eval(v1.x, sA, sB); v1.y = hb_eval(v1.y, sA, sB);
    v1.z = hb_eval(v1.z, sA, sB); v1.w = hb_eval(v1.w, sA, sB);
    v2.x = hb_eval(v2.x, sA, sB); v2.y = hb_eval(v2.y, sA, sB);
    v2.z = hb_eval(v2.z, sA, sB); v2.w = hb_eval(v2.w, sA, sB);
    v3.x = hb_eval(v3.x, sA, sB); v3.y = hb_eval(v3.y, sA, sB);
    v3.z = hb_eval(v3.z, sA, sB); v3.w = hb_eval(v3.w, sA, sB);

    __stcs(o4 + i0, v0);
    __stcs(o4 + i1, v1);
    __stcs(o4 + i2, v2);
    __stcs(o4 + i3, v3);
}

// Tail kernel: scalar grid-stride over [start, n). Only launched if needed
// (not hit for the 64x4096x256 shape: 67,108,864 = 16384 * 4096 exactly).
__global__ void __launch_bounds__(NTHR)
hybrid_basis_tail(const float* __restrict__ x, float* __restrict__ out,
                  const float* __restrict__ wc, const float* __restrict__ sc,
                  const float* __restrict__ al, int start, int n)
{
    __shared__ float sA[17];
    __shared__ float sB[17];
    hb_lut_init(wc, sc, al, sA, sB);

    for (int t = start + blockIdx.x * blockDim.x + threadIdx.x; t < n;
         t += gridDim.x * blockDim.x) {
        out[t] = hb_eval(x[t], sA, sB);
    }
}

extern "C" void kernel_launch(void* const* d_in, const int* in_sizes, int n_in,
                              void* d_out, int out_size) {
    const float* x  = nullptr;
    const float* wc = nullptr;
    const float* sc = nullptr;
    const float* al = nullptr;
    long long max_sz = -1;
    int max_idx = 0;
    for (int i = 0; i < n_in; ++i) {
        if ((long long)in_sizes[i] > max_sz) { max_sz = in_sizes[i]; max_idx = i; }
    }
    for (int i = 0; i < n_in; ++i) {
        if (i == max_idx)            x  = (const float*)d_in[i];
        else if (in_sizes[i] == 5)   wc = (const float*)d_in[i];
        else if (in_sizes[i] == 8)   sc = (const float*)d_in[i];
        else if (in_sizes[i] == 1)   al = (const float*)d_in[i];
    }

    int n = out_size;
    int elems_per_block = NTHR * VPT * 4;          // 4096 elements per block
    int nblocks = n / elems_per_block;             // exact-tiled portion
    int covered = nblocks * elems_per_block;

    if (nblocks > 0) {
        hybrid_basis_main<<<nblocks, NTHR>>>((const float4*)x, (float4*)d_out, wc, sc, al);
    }
    if (covered < n) {
        int tail = n - covered;
        int tblocks = (tail + NTHR - 1) / NTHR;
        if (tblocks > 1024) tblocks = 1024;
        hybrid_basis_tail<<<tblocks, NTHR>>>(x, (float*)d_out, wc, sc, al, covered, n);
    }
}

// round 17
// speedup vs baseline: 1.0283x; 1.0283x over previous
#include <cuda_runtime.h>
#include <math.h>

// HybridBasisFunction: out = wavelet(xc) + sigmoid(alpha) * spline(xc), xc = clamp(x,0,1)
//
// Piecewise-affine reformulation: with j = floor(16*xc) (j in [0,16]),
//   - wavelet level-l sign = +1 iff bit (4-l) of j is 0   (exact: *16 is exact in fp32)
//   - spline segment k = j>>2 is constant within a bucket, lerp is affine in xc
// => out = A[j] + B[j]*xc with a 17-entry LUT in shared memory (conflict-free).
//
// R17: block-shape probe at the validated 16KB tile optimum. NTHR 256->512,
// VPT 4->2: same 16KB contiguous tile, same 16384-block grid, same in-flight
// bytes per CTA, but 16 warps/CTA (4 CTAs/SM) and one wide 32KB read sweep
// per tile before stores. Tests whether CTA shape matters at the optimum.
// Tile-size curve (kernel us): 64KB 79.1; 32KB 77.8; 16KB 76.0-76.8 (min);
// 8KB 77.6. All other axes previously measured neutral or worse.

#define NTHR 512
#define VPT  2    // float4 per thread; 16KB contiguous tile per CTA

__device__ __forceinline__ float hb_eval(float v, const float* __restrict__ sA,
                                         const float* __restrict__ sB) {
    float xc = fminf(fmaxf(v, 0.0f), 1.0f);
    int j = (int)(xc * 16.0f);           // exact; j in [0,16]
    return fmaf(sB[j], xc, sA[j]);
}

__device__ __forceinline__ void hb_lut_init(const float* __restrict__ wc,
                                            const float* __restrict__ sc,
                                            const float* __restrict__ al,
                                            float* __restrict__ sA,
                                            float* __restrict__ sB) {
    if (threadIdx.x < 17) {
        int j = threadIdx.x;
        float sig = 1.0f / (1.0f + expf(-al[0]));
        float A, B;
        if (j < 16) {
            float wv = wc[0];
            wv += ((j >> 3) & 1) ? -wc[1] : wc[1];
            wv += ((j >> 2) & 1) ? -wc[2] : wc[2];
            wv += ((j >> 1) & 1) ? -wc[3] : wc[3];
            wv += ( j       & 1) ? -wc[4] : wc[4];
            int k = j >> 2;
            float c0 = sc[k], c1 = sc[k + 1];
            float d  = sig * (c1 - c0);
            A = wv + sig * c0 - (float)k * d;
            B = 4.0f * d;
        } else {
            A = wc[0] + sig * sc[4];   // xc == 1.0 exactly
            B = 0.0f;
        }
        sA[j] = A;
        sB[j] = B;
    }
    __syncthreads();
}

// Main kernel: each block owns a contiguous tile of NTHR*VPT float4s, exact fit.
__global__ void __launch_bounds__(NTHR)
hybrid_basis_main(const float4* __restrict__ x4, float4* __restrict__ o4,
                  const float* __restrict__ wc, const float* __restrict__ sc,
                  const float* __restrict__ al)
{
    __shared__ float sA[17];
    __shared__ float sB[17];
    hb_lut_init(wc, sc, al, sA, sB);

    int base = blockIdx.x * (NTHR * VPT) + threadIdx.x;

    int i0 = base;
    int i1 = base + NTHR;

    float4 v0 = __ldcs(x4 + i0);
    float4 v1 = __ldcs(x4 + i1);

    v0.x = hb_eval(v0.x, sA, sB); v0.y = hb_eval(v0.y, sA, sB);
    v0.z = hb_eval(v0.z, sA, sB); v0.w = hb_eval(v0.w, sA, sB);
    v1.x = hb_eval(v1.x, sA, sB); v1.y = hb_eval(v1.y, sA, sB);
    v1.z = hb_eval(v1.z, sA, sB); v1.w = hb_eval(v1.w, sA, sB);

    __stcs(o4 + i0, v0);
    __stcs(o4 + i1, v1);
}

// Tail kernel: scalar grid-stride over [start, n). Only launched if needed
// (not hit for the 64x4096x256 shape: 67,108,864 = 16384 * 4096 exactly).
__global__ void __launch_bounds__(NTHR)
hybrid_basis_tail(const float* __restrict__ x, float* __restrict__ out,
                  const float* __restrict__ wc, const float* __restrict__ sc,
                  const float* __restrict__ al, int start, int n)
{
    __shared__ float sA[17];
    __shared__ float sB[17];
    hb_lut_init(wc, sc, al, sA, sB);

    for (int t = start + blockIdx.x * blockDim.x + threadIdx.x; t < n;
         t += gridDim.x * blockDim.x) {
        out[t] = hb_eval(x[t], sA, sB);
    }
}

extern "C" void kernel_launch(void* const* d_in, const int* in_sizes, int n_in,
                              void* d_out, int out_size) {
    const float* x  = nullptr;
    const float* wc = nullptr;
    const float* sc = nullptr;
    const float* al = nullptr;
    long long max_sz = -1;
    int max_idx = 0;
    for (int i = 0; i < n_in; ++i) {
        if ((long long)in_sizes[i] > max_sz) { max_sz = in_sizes[i]; max_idx = i; }
    }
    for (int i = 0; i < n_in; ++i) {
        if (i == max_idx)            x  = (const float*)d_in[i];
        else if (in_sizes[i] == 5)   wc = (const float*)d_in[i];
        else if (in_sizes[i] == 8)   sc = (const float*)d_in[i];
        else if (in_sizes[i] == 1)   al = (const float*)d_in[i];
    }

    int n = out_size;
    int elems_per_block = NTHR * VPT * 4;          // 4096 elements per block
    int nblocks = n / elems_per_block;             // exact-tiled portion
    int covered = nblocks * elems_per_block;

    if (nblocks > 0) {
        hybrid_basis_main<<<nblocks, NTHR>>>((const float4*)x, (float4*)d_out, wc, sc, al);
    }
    if (covered < n) {
        int tail = n - covered;
        int tblocks = (tail + NTHR - 1) / NTHR;
        if (tblocks > 1024) tblocks = 1024;
        hybrid_basis_tail<<<tblocks, NTHR>>>(x, (float*)d_out, wc, sc, al, covered, n);
    }
}